// round 1
// baseline (speedup 1.0000x reference)
#include <cuda_runtime.h>
#include <cuda_bf16.h>
#include <cstdint>

#define N_NODES 100000
#define DEG 16
#define D 128
#define TILE_M 64
#define STRIDE 260           // 256 K + 4 pad -> conflict-free A-frag LDS
#define NTHREADS 256

__device__ __forceinline__ unsigned tf32_of(float f) {
    unsigned r;
    asm("cvt.rna.tf32.f32 %0, %1;" : "=r"(r) : "f"(f));
    return r;
}

__device__ __forceinline__ void mma_tf32(float c[4], const unsigned a[4], const unsigned b[2]) {
    asm volatile(
        "mma.sync.aligned.m16n8k8.row.col.f32.tf32.tf32.f32 "
        "{%0,%1,%2,%3},{%4,%5,%6,%7},{%8,%9},{%0,%1,%2,%3};\n"
        : "+f"(c[0]), "+f"(c[1]), "+f"(c[2]), "+f"(c[3])
        : "r"(a[0]), "r"(a[1]), "r"(a[2]), "r"(a[3]),
          "r"(b[0]), "r"(b[1]));
}

extern __shared__ float smem_raw[];

__global__ void __launch_bounds__(NTHREADS)
gconv_fused_kernel(const int* __restrict__ nbr,
                   const float* __restrict__ x,
                   const float* __restrict__ W1,
                   const float* __restrict__ b1,
                   const float* __restrict__ W2,
                   const float* __restrict__ b2,
                   float* __restrict__ out)
{
    float* As = smem_raw;                       // [TILE_M][STRIDE], tf32 bit-patterns
    float* bias_s = smem_raw + TILE_M * STRIDE; // [128]
    unsigned* Asu = reinterpret_cast<unsigned*>(As);

    const int tid  = threadIdx.x;
    const int warp = tid >> 5;
    const int lane = tid & 31;
    const int m0   = blockIdx.x * TILE_M;

    if (tid < D) bias_s[tid] = b1[tid] + b2[tid];

    // ---------------- Phase 1: load x-tile + gather-sum neighbors ----------------
    const float4* x4 = reinterpret_cast<const float4*>(x);
    for (int m = warp; m < TILE_M; m += 8) {
        const int node = m0 + m;
        float4 xv = make_float4(0.f, 0.f, 0.f, 0.f);
        float4 acc = make_float4(0.f, 0.f, 0.f, 0.f);
        if (node < N_NODES) {
            xv = __ldg(x4 + (size_t)node * 32 + lane);
            int idx = 0;
            if (lane < DEG) idx = __ldg(nbr + (size_t)node * DEG + lane);
            #pragma unroll
            for (int j = 0; j < DEG; j++) {
                int nj = __shfl_sync(0xffffffffu, idx, j);
                float4 v = __ldg(x4 + (size_t)nj * 32 + lane);
                acc.x += v.x; acc.y += v.y; acc.z += v.z; acc.w += v.w;
            }
        }
        uint4 xt = make_uint4(tf32_of(xv.x), tf32_of(xv.y), tf32_of(xv.z), tf32_of(xv.w));
        uint4 at = make_uint4(tf32_of(acc.x), tf32_of(acc.y), tf32_of(acc.z), tf32_of(acc.w));
        *reinterpret_cast<uint4*>(&As[m * STRIDE + 4 * lane])       = xt;
        *reinterpret_cast<uint4*>(&As[m * STRIDE + D + 4 * lane])   = at;
    }
    __syncthreads();

    // ---------------- Phase 2: tf32 MMA, out = relu(A @ [W1|W2]^T + b) ----------------
    const int wm = warp >> 2;   // 0..1  -> 32 rows each
    const int wn = warp & 3;    // 0..3  -> 32 cols each
    const int g  = lane >> 2;   // groupID
    const int t  = lane & 3;    // threadID_in_group

    float c[2][4][4];
    #pragma unroll
    for (int mi = 0; mi < 2; mi++)
        #pragma unroll
        for (int ni = 0; ni < 4; ni++)
            #pragma unroll
            for (int r = 0; r < 4; r++) c[mi][ni][r] = 0.f;

    #pragma unroll 4
    for (int ks = 0; ks < 32; ks++) {
        const int k0 = ks * 8;
        // A fragments from smem
        unsigned a[2][4];
        #pragma unroll
        for (int mi = 0; mi < 2; mi++) {
            const int r0 = wm * 32 + mi * 16 + g;
            const int col = k0 + t;
            a[mi][0] = Asu[r0 * STRIDE + col];
            a[mi][1] = Asu[(r0 + 8) * STRIDE + col];
            a[mi][2] = Asu[r0 * STRIDE + col + 4];
            a[mi][3] = Asu[(r0 + 8) * STRIDE + col + 4];
        }
        // B fragments from global W (L1-resident, 128KB total)
        const float* Wsel = (k0 < D) ? W1 : W2;
        const int kk = k0 & (D - 1);
        unsigned b[4][2];
        #pragma unroll
        for (int ni = 0; ni < 4; ni++) {
            const int o = wn * 32 + ni * 8 + g;
            b[ni][0] = tf32_of(__ldg(Wsel + o * D + kk + t));
            b[ni][1] = tf32_of(__ldg(Wsel + o * D + kk + 4 + t));
        }
        #pragma unroll
        for (int mi = 0; mi < 2; mi++)
            #pragma unroll
            for (int ni = 0; ni < 4; ni++)
                mma_tf32(c[mi][ni], a[mi], b[ni]);
    }

    // ---------------- Epilogue: bias + relu + store ----------------
    #pragma unroll
    for (int mi = 0; mi < 2; mi++) {
        const int node0 = m0 + wm * 32 + mi * 16 + g;
        const int node1 = node0 + 8;
        #pragma unroll
        for (int ni = 0; ni < 4; ni++) {
            const int col = wn * 32 + ni * 8 + 2 * t;
            const float bs0 = bias_s[col];
            const float bs1 = bias_s[col + 1];
            if (node0 < N_NODES) {
                float2 v0;
                v0.x = fmaxf(c[mi][ni][0] + bs0, 0.f);
                v0.y = fmaxf(c[mi][ni][1] + bs1, 0.f);
                *reinterpret_cast<float2*>(&out[(size_t)node0 * D + col]) = v0;
            }
            if (node1 < N_NODES) {
                float2 v1;
                v1.x = fmaxf(c[mi][ni][2] + bs0, 0.f);
                v1.y = fmaxf(c[mi][ni][3] + bs1, 0.f);
                *reinterpret_cast<float2*>(&out[(size_t)node1 * D + col]) = v1;
            }
        }
    }
}

extern "C" void kernel_launch(void* const* d_in, const int* in_sizes, int n_in,
                              void* d_out, int out_size)
{
    const int*   nbr = (const int*)d_in[0];
    const float* x   = (const float*)d_in[1];
    const float* W1  = (const float*)d_in[2];
    const float* b1  = (const float*)d_in[3];
    const float* W2  = (const float*)d_in[4];
    const float* b2  = (const float*)d_in[5];
    float*       out = (float*)d_out;

    const int smem_bytes = (TILE_M * STRIDE + D) * (int)sizeof(float); // 67,584 B
    static bool attr_set = false;
    // idempotent, deterministic, not a stream op — safe under graph capture
    cudaFuncSetAttribute(gconv_fused_kernel,
                         cudaFuncAttributeMaxDynamicSharedMemorySize, smem_bytes);
    (void)attr_set;

    const int grid = (N_NODES + TILE_M - 1) / TILE_M; // 1563
    gconv_fused_kernel<<<grid, NTHREADS, smem_bytes>>>(nbr, x, W1, b1, W2, b2, out);
}